// round 4
// baseline (speedup 1.0000x reference)
#include <cuda_runtime.h>
#include <cuda_bf16.h>
#include <cstdint>

#define Bn   256
#define Tn   64
#define Sn   10
#define Hn   128
#define BTn  (Bn*Tn)            // 16384
#define BTSn (Bn*Tn*Sn)         // 163840
#define SHn  (Sn*Hn)            // 1280

static const size_t HSEQ_SZ  = (size_t)Bn*Tn*Sn*Hn;                   // 20971520
static const size_t LOSS_IDX = (size_t)Bn*Tn*Sn*Hn + 2ull*Bn*Sn*Hn;   // 21626880

// ---------------- device scratch (static, allocation-free) ----------------
__device__ float g_px8 [(size_t)BTn * 1024];   // raw px per gate
__device__ float g_pxg [(size_t)BTn * 768];    // folded channels
__device__ float g_qtmp[(size_t)BTSn * Hn];
__device__ float g_qp  [(size_t)BTSn * Hn];
__device__ float g_pk  [(size_t)Bn*Tn*Sn*Hn];
__device__ float g_pv  [(size_t)Bn*Tn*Sn*Hn];
__device__ int   g_nv  [Tn];
__device__ float g_losspart[Bn];

__device__ __forceinline__ float sigf(float x) { return 1.f / (1.f + expf(-x)); }

// ---------------- nv[t] precompute ----------------
__global__ void nv_kernel(const int* __restrict__ kl) {
    int t = threadIdx.x;
    int c = 0;
    for (int b = 0; b < Bn; b++) c += (t < kl[b]) ? 1 : 0;
    g_nv[t] = c;
}

// ---------------- fp32 GEMM: C tile 128x128, K=128. grid.y picks B matrix + col group
__global__ __launch_bounds__(256) void gemm128(
    const float* __restrict__ A, int lda,
    const float* __restrict__ B0, int bstride,
    const float* __restrict__ bias,
    float* __restrict__ C, int ldc)
{
    const float* Bm = B0 + (size_t)blockIdx.y * bstride;
    __shared__ float  As[128][17];
    __shared__ float4 Bs[16][32];
    int tid = threadIdx.x;
    int tx = tid & 15, ty = tid >> 4;
    size_t row0 = (size_t)blockIdx.x * 128;

    float acc[8][8];
    #pragma unroll
    for (int i = 0; i < 8; i++)
        #pragma unroll
        for (int j = 0; j < 8; j++) acc[i][j] = 0.f;

    for (int k0 = 0; k0 < 128; k0 += 16) {
        #pragma unroll
        for (int j = 0; j < 8; j++) {
            int idx = j * 256 + tid;
            int r = idx >> 4, kk = idx & 15;
            As[r][kk] = A[(row0 + r) * (size_t)lda + k0 + kk];
        }
        #pragma unroll
        for (int i = 0; i < 2; i++) {
            int idx = i * 256 + tid;
            int kk = idx >> 5, c4 = idx & 31;
            Bs[kk][c4] = *reinterpret_cast<const float4*>(Bm + (size_t)(k0 + kk) * 128 + c4 * 4);
        }
        __syncthreads();
        #pragma unroll
        for (int kk = 0; kk < 16; kk++) {
            float a[8];
            #pragma unroll
            for (int i = 0; i < 8; i++) a[i] = As[ty * 8 + i][kk];
            float4 bv0 = Bs[kk][tx * 2];
            float4 bv1 = Bs[kk][tx * 2 + 1];
            float bjs[8] = {bv0.x, bv0.y, bv0.z, bv0.w, bv1.x, bv1.y, bv1.z, bv1.w};
            #pragma unroll
            for (int i = 0; i < 8; i++)
                #pragma unroll
                for (int j = 0; j < 8; j++)
                    acc[i][j] = fmaf(a[i], bjs[j], acc[i][j]);
        }
        __syncthreads();
    }
    float bb[8] = {0,0,0,0,0,0,0,0};
    if (bias) {
        #pragma unroll
        for (int j = 0; j < 8; j++) bb[j] = bias[tx * 8 + j];
    }
    #pragma unroll
    for (int i = 0; i < 8; i++) {
        size_t gr = row0 + ty * 8 + i;
        float* cp = C + gr * (size_t)ldc + blockIdx.y * 128 + tx * 8;
        float4 o0 = make_float4(acc[i][0]+bb[0], acc[i][1]+bb[1], acc[i][2]+bb[2], acc[i][3]+bb[3]);
        float4 o1 = make_float4(acc[i][4]+bb[4], acc[i][5]+bb[5], acc[i][6]+bb[6], acc[i][7]+bb[7]);
        *reinterpret_cast<float4*>(cp)     = o0;
        *reinterpret_cast<float4*>(cp + 4) = o1;
    }
}

// ---------------- fold biases / timestamp gates ----------------
// channels: 0..2: px[g]+bg[g]; 3: px3+Tt*Wts4+Dt*Wts5+bg3; 4: T1*D1; 5: T2*D2
__global__ __launch_bounds__(256) void prep_kernel(
    const float* __restrict__ inputs, const float* __restrict__ Wts, const float* __restrict__ bg)
{
    int idx = blockIdx.x * 256 + threadIdx.x;
    int r = idx >> 7, k = idx & 127;
    float Tt = inputs[(size_t)r * 130];
    float Dt = inputs[(size_t)r * 130 + 1];
    const float* px = g_px8 + (size_t)r * 1024;
    float* o = g_pxg + (size_t)r * 768;
    o[k]        = px[k]        + bg[k];
    o[Hn + k]   = px[Hn + k]   + bg[Hn + k];
    o[2*Hn + k] = px[2*Hn + k] + bg[2*Hn + k];
    o[3*Hn + k] = px[3*Hn + k] + fmaf(Tt, Wts[4*Hn + k], fmaf(Dt, Wts[5*Hn + k], bg[3*Hn + k]));
    float T1 = sigf(px[4*Hn + k] + sigf(Tt * Wts[k])        + bg[4*Hn + k]);
    float T2 = sigf(px[5*Hn + k] + sigf(Tt * Wts[Hn + k])   + bg[5*Hn + k]);
    float D1 = sigf(px[6*Hn + k] + sigf(Dt * Wts[2*Hn + k]) + bg[6*Hn + k]);
    float D2 = sigf(px[7*Hn + k] + sigf(Dt * Wts[3*Hn + k]) + bg[7*Hn + k]);
    o[4*Hn + k] = T1 * D1;
    o[5*Hn + k] = T2 * D2;
}

// ---------------- recurrent kernel: one block per batch ----------------
__global__ __launch_bounds__(512, 2) void recur_kernel(
    const float* __restrict__ Wh,
    const float* __restrict__ Wattn,
    const float* __restrict__ battn,
    const int*   __restrict__ kl_arr,
    const float* __restrict__ y_all,
    float* __restrict__ out)
{
    const int b    = blockIdx.x;
    const int tid  = threadIdx.x;
    const int lane = tid & 31;
    const int warp = tid >> 5;
    const int kl   = kl_arr[b];

    __shared__ float h_sm[SHn];      // h state (== h_new on executed steps)
    __shared__ float c_sm[SHn];
    __shared__ float qp_sm[SHn];
    __shared__ float ctx_sm[SHn];
    __shared__ float at_sm[SHn];
    __shared__ float pre_sm[4][SHn];
    __shared__ float sc_sm[Sn][Tn];
    __shared__ float nvinv_sm[Tn];
    __shared__ float red_sm[16];

    for (int i = tid; i < SHn; i += 512) { h_sm[i] = 0.f; c_sm[i] = 0.f; }
    if (tid < Tn) nvinv_sm[tid] = 1.f / (float)max(g_nv[tid], 1);
    __syncthreads();

    const size_t bbase = (size_t)b * Tn * Sn * Hn;
    float*       pkb  = g_pk  + bbase;
    float*       pvb  = g_pv  + bbase;
    const float* qpb  = g_qp  + bbase;
    const float* pxb  = g_pxg + (size_t)b * Tn * 768;
    float*       hseq = out + bbase;
    float lsum = 0.f;
    const float scale = 0.088388347648318447f; // 1/sqrt(128)

    for (int t = 0; t < kl; t++) {
        const float* qpt = qpb + (size_t)t * SHn;
        const float* pxt = pxb + (size_t)t * 768;
        for (int i = tid; i < SHn; i += 512) qp_sm[i] = qpt[i];
        __syncthreads();   // qp ready; prior step's pk/pv global writes visible

        if (t > 0) {
            // scores: one warp per (s, t') pair
            for (int p = warp; p < Sn * t; p += 16) {
                int tp = p / Sn, s = p - tp * Sn;
                const float* pkrow = pkb + ((size_t)tp * Sn + s) * Hn;
                const float* q = qp_sm + s * Hn;
                float a = 0.f;
                #pragma unroll
                for (int h = 0; h < 4; h++) a = fmaf(q[lane + h*32], pkrow[lane + h*32], a);
                #pragma unroll
                for (int o = 16; o; o >>= 1) a += __shfl_xor_sync(0xffffffffu, a, o);
                if (lane == 0) sc_sm[s][tp] = a * scale;
            }
            __syncthreads();
            // softmax over t' < t, warp s
            if (warp < Sn) {
                float* sc = sc_sm[warp];
                float m = -1e30f;
                for (int tp = lane; tp < t; tp += 32) m = fmaxf(m, sc[tp]);
                #pragma unroll
                for (int o = 16; o; o >>= 1) m = fmaxf(m, __shfl_xor_sync(0xffffffffu, m, o));
                float sum = 0.f;
                for (int tp = lane; tp < t; tp += 32) { float e = __expf(sc[tp] - m); sc[tp] = e; sum += e; }
                #pragma unroll
                for (int o = 16; o; o >>= 1) sum += __shfl_xor_sync(0xffffffffu, sum, o);
                float inv = 1.f / sum;
                for (int tp = lane; tp < t; tp += 32) sc[tp] *= inv;
            }
            __syncthreads();
            // ctx = weights @ pv
            for (int i = tid; i < SHn; i += 512) {
                int s = i >> 7;
                const float* pvp = pvb + i;
                float a = 0.f;
                for (int tp = 0; tp < t; tp++) a = fmaf(sc_sm[s][tp], pvp[(size_t)tp * SHn], a);
                ctx_sm[i] = a;
            }
            __syncthreads();
            // at = ctx @ Wattn[3] + battn[3]
            {
                int j = tid >> 7, k = tid & 127;
                const float* W3 = Wattn + 3 * Hn * Hn + k;
                bool has2 = (j < 2);
                const float* c0 = ctx_sm + j * Hn;
                const float* c1 = ctx_sm + (j + 4) * Hn;
                const float* c2 = ctx_sm + (has2 ? (j + 8) : j) * Hn;
                float a0 = 0.f, a1 = 0.f, a2 = 0.f;
                for (int h4 = 0; h4 < Hn; h4 += 4) {
                    float w0 = W3[(h4+0)*Hn], w1 = W3[(h4+1)*Hn], w2 = W3[(h4+2)*Hn], w3 = W3[(h4+3)*Hn];
                    float4 v0 = *reinterpret_cast<const float4*>(c0 + h4);
                    a0 = fmaf(v0.x,w0, fmaf(v0.y,w1, fmaf(v0.z,w2, fmaf(v0.w,w3, a0))));
                    float4 v1 = *reinterpret_cast<const float4*>(c1 + h4);
                    a1 = fmaf(v1.x,w0, fmaf(v1.y,w1, fmaf(v1.z,w2, fmaf(v1.w,w3, a1))));
                    if (has2) {
                        float4 v2 = *reinterpret_cast<const float4*>(c2 + h4);
                        a2 = fmaf(v2.x,w0, fmaf(v2.y,w1, fmaf(v2.z,w2, fmaf(v2.w,w3, a2))));
                    }
                }
                float bb = battn[3 * Hn + k];
                at_sm[j * Hn + k]       = a0 + bb;
                at_sm[(j + 4) * Hn + k] = a1 + bb;
                if (has2) at_sm[(j + 8) * Hn + k] = a2 + bb;
            }
        } else {
            for (int i = tid; i < SHn; i += 512) at_sm[i] = 1.f;
        }

        // ph = h @ Wh[g] + folded px   (thread = (g,k); s register-blocked; h broadcast from smem)
        {
            int g = tid >> 7, k = tid & 127;
            const float* Wg = Wh + (size_t)g * Hn * Hn + k;
            float acc[Sn];
            #pragma unroll
            for (int s = 0; s < Sn; s++) acc[s] = 0.f;
            for (int h4 = 0; h4 < Hn; h4 += 4) {
                float w0 = Wg[(h4+0)*Hn], w1 = Wg[(h4+1)*Hn], w2 = Wg[(h4+2)*Hn], w3 = Wg[(h4+3)*Hn];
                #pragma unroll
                for (int s = 0; s < Sn; s++) {
                    float4 hv = *reinterpret_cast<const float4*>(h_sm + s * Hn + h4);
                    acc[s] = fmaf(hv.x,w0, fmaf(hv.y,w1, fmaf(hv.z,w2, fmaf(hv.w,w3, acc[s]))));
                }
            }
            float p = pxt[g * Hn + k];
            #pragma unroll
            for (int s = 0; s < Sn; s++) pre_sm[g][s * Hn + k] = acc[s] + p;
        }
        __syncthreads();   // pre_sm/at_sm ready; h_sm reads done -> safe to overwrite

        // gates + state update + hseq + loss (mask true on all executed steps)
        {
            float yv = y_all[b * Tn + t];
            float invnv = nvinv_sm[t];
            float lstep = 0.f;
            for (int i = tid; i < SHn; i += 512) {
                int k = i & 127;
                float it  = sigf(pre_sm[0][i]);
                float ft  = sigf(pre_sm[1][i]);
                float ctd = tanhf(pre_sm[2][i]);
                float ot  = sigf(pre_sm[3][i]);
                float at  = at_sm[i];
                float td1 = pxt[4 * Hn + k];
                float td2 = pxt[5 * Hn + k];
                float itp = it * at, ftp = ft * at;
                float c = c_sm[i];
                float base = ftp * c;
                float ic = itp * ctd;
                float chat = fmaf(ic, td1, base);
                float cnew = fmaf(ic, td2, base);
                float hnew = ot * tanhf(chat);
                c_sm[i] = cnew;
                h_sm[i] = hnew;
                hseq[(size_t)t * SHn + i] = hnew;
                float pcl = fminf(fmaxf(hnew, 1e-7f), 1.f - 1e-7f);
                lstep += -(yv * logf(pcl) + (1.f - yv) * log1pf(-pcl));
            }
            lsum = fmaf(lstep, invnv * (1.f / (float)SHn), lsum);
        }
        __syncthreads();   // h_sm (= h_new) ready for pk/pv + next-step ph

        // pk[t] = h@Wattn1 + battn1 ; pv[t] = h@Wattn2 + battn2
        {
            int m = tid >> 8, j = (tid >> 7) & 1, k = tid & 127;
            const float* W = Wattn + (size_t)(1 + m) * Hn * Hn + k;
            float acc[5];
            #pragma unroll
            for (int q = 0; q < 5; q++) acc[q] = 0.f;
            for (int h4 = 0; h4 < Hn; h4 += 4) {
                float w0 = W[(h4+0)*Hn], w1 = W[(h4+1)*Hn], w2 = W[(h4+2)*Hn], w3 = W[(h4+3)*Hn];
                #pragma unroll
                for (int q = 0; q < 5; q++) {
                    float4 hv = *reinterpret_cast<const float4*>(h_sm + (2*q + j) * Hn + h4);
                    acc[q] = fmaf(hv.x,w0, fmaf(hv.y,w1, fmaf(hv.z,w2, fmaf(hv.w,w3, acc[q]))));
                }
            }
            float bb = battn[(1 + m) * Hn + k];
            float* dst = (m == 0) ? pkb : pvb;
            #pragma unroll
            for (int q = 0; q < 5; q++)
                dst[((size_t)t * Sn + (2*q + j)) * Hn + k] = acc[q] + bb;
        }
        // no trailing sync needed: next-iter top sync orders these writes
    }

    // zero tail of hseq for masked steps
    for (size_t i = tid; i < (size_t)(Tn - kl) * SHn; i += 512)
        hseq[(size_t)kl * SHn + i] = 0.f;

    // final h, c
    {
        float* hout = out + HSEQ_SZ + (size_t)b * SHn;
        float* cout = out + HSEQ_SZ + (size_t)Bn * SHn + (size_t)b * SHn;
        __syncthreads();
        for (int i = tid; i < SHn; i += 512) { hout[i] = h_sm[i]; cout[i] = c_sm[i]; }
    }

    // loss partial (deterministic final reduce in separate kernel)
    #pragma unroll
    for (int o = 16; o; o >>= 1) lsum += __shfl_xor_sync(0xffffffffu, lsum, o);
    if (lane == 0) red_sm[warp] = lsum;
    __syncthreads();
    if (tid == 0) {
        float s = 0.f;
        #pragma unroll
        for (int w = 0; w < 16; w++) s += red_sm[w];
        g_losspart[b] = s;
    }
}

// ---------------- deterministic loss reduction ----------------
__global__ void loss_final(float* __restrict__ out) {
    if (threadIdx.x == 0) {
        float s = 0.f;
        for (int b = 0; b < Bn; b++) s += g_losspart[b];
        out[LOSS_IDX] = s;
    }
}

extern "C" void kernel_launch(void* const* d_in, const int* in_sizes, int n_in,
                              void* d_out, int out_size) {
    const float* inputs = (const float*)d_in[0];
    const float* x_q    = (const float*)d_in[1];
    const float* y_all  = (const float*)d_in[2];
    const int*   kl     = (const int*)  d_in[3];
    const float* Wx     = (const float*)d_in[4];
    const float* Wh     = (const float*)d_in[5];
    const float* Wts    = (const float*)d_in[6];
    const float* bg     = (const float*)d_in[7];
    const float* Wa     = (const float*)d_in[8];
    const float* ba     = (const float*)d_in[9];
    const float* Wattn  = (const float*)d_in[10];
    const float* battn  = (const float*)d_in[11];
    float* out = (float*)d_out;

    float *px8, *qtmp, *qp;
    cudaGetSymbolAddress((void**)&px8,  g_px8);
    cudaGetSymbolAddress((void**)&qtmp, g_qtmp);
    cudaGetSymbolAddress((void**)&qp,   g_qp);

    nv_kernel<<<1, 64>>>(kl);

    // px8 = xt @ Wx[g], g in grid.y
    gemm128<<<dim3(BTn/128, 8), 256>>>(inputs + 2, 130, Wx, Hn*Hn, nullptr, px8, 1024);
    // qtmp = x_q @ Wa + ba
    gemm128<<<dim3(BTSn/128, 1), 256>>>(x_q, Hn, Wa, 0, ba, qtmp, Hn);
    // qp = qtmp @ Wattn[0] + battn[0]
    gemm128<<<dim3(BTSn/128, 1), 256>>>(qtmp, Hn, Wattn, 0, battn, qp, Hn);
    // fold biases / timestamp gates
    prep_kernel<<<BTn*Hn/256, 256>>>(inputs, Wts, bg);
    // recurrence: one block per batch
    recur_kernel<<<Bn, 512>>>(Wh, Wattn, battn, kl, y_all, out);
    // deterministic loss sum
    loss_final<<<1, 32>>>(out);
}

// round 5
// speedup vs baseline: 1.1809x; 1.1809x over previous
#include <cuda_runtime.h>
#include <cuda_bf16.h>
#include <cstdint>

#define Bn   256
#define Tn   64
#define Sn   10
#define Hn   128
#define BTn  (Bn*Tn)            // 16384
#define BTSn (Bn*Tn*Sn)         // 163840
#define SHn  (Sn*Hn)            // 1280

static const size_t HSEQ_SZ  = (size_t)Bn*Tn*Sn*Hn;                   // 20971520
static const size_t LOSS_IDX = (size_t)Bn*Tn*Sn*Hn + 2ull*Bn*Sn*Hn;   // 21626880

// ---------------- device scratch (static, allocation-free) ----------------
__device__ float g_px8 [(size_t)BTn * 1024];   // raw px per gate
__device__ float g_pxg [(size_t)BTn * 768];    // folded channels
__device__ float g_qp  [(size_t)BTSn * Hn];
__device__ float g_pk  [(size_t)Bn*Tn*Sn*Hn];
__device__ float g_pv  [(size_t)Bn*Tn*Sn*Hn];
__device__ float g_wfused[Hn*Hn];
__device__ float g_bfused[Hn];
__device__ int   g_nv  [Tn];
__device__ int   g_order[Bn];
__device__ float g_losspart[Bn];

__device__ __forceinline__ float sigf(float x) { return 1.f / (1.f + expf(-x)); }

// ---------------- nv[t] precompute ----------------
__global__ void nv_kernel(const int* __restrict__ kl) {
    int t = threadIdx.x;
    int c = 0;
    for (int b = 0; b < Bn; b++) c += (t < kl[b]) ? 1 : 0;
    g_nv[t] = c;
}

// ---------------- kl-balanced block ordering ----------------
// Sort batches by kl desc (stable counting sort). bid<148 gets rank bid;
// bid>=148 gets rank 403-bid, so co-resident pairs (bid, bid+148) via
// LUT_classic[bid%148] have kl sums ~= max_kl (balanced makespan).
__global__ void order_kernel(const int* __restrict__ kl) {
    if (threadIdx.x != 0) return;
    int cnt[Tn + 1];
    for (int v = 0; v <= Tn; v++) cnt[v] = 0;
    for (int b = 0; b < Bn; b++) cnt[kl[b]]++;
    int off[Tn + 1];
    int acc = 0;
    for (int v = Tn; v >= 0; v--) { off[v] = acc; acc += cnt[v]; }
    for (int b = 0; b < Bn; b++) {
        int r = off[kl[b]]++;                  // rank in desc order, stable
        int bid = (r < 148) ? r : (403 - r);   // pair rank r with rank 403-bid
        g_order[bid] = b;
    }
}

// ---------------- bfused = ba @ Wattn0 + battn0 ----------------
__global__ void bfuse_kernel(const float* __restrict__ ba,
                             const float* __restrict__ Wattn,
                             const float* __restrict__ battn) {
    int k = threadIdx.x;
    float a = battn[k];
    for (int h = 0; h < Hn; h++) a = fmaf(ba[h], Wattn[h * Hn + k], a);
    g_bfused[k] = a;
}

// ---------------- fp32 GEMM: C tile 128x128, K=128. grid.y picks B matrix + col group
__global__ __launch_bounds__(256) void gemm128(
    const float* __restrict__ A, int lda,
    const float* __restrict__ B0, int bstride,
    const float* __restrict__ bias,
    float* __restrict__ C, int ldc)
{
    const float* Bm = B0 + (size_t)blockIdx.y * bstride;
    __shared__ float  As[128][17];
    __shared__ float4 Bs[16][32];
    int tid = threadIdx.x;
    int tx = tid & 15, ty = tid >> 4;
    size_t row0 = (size_t)blockIdx.x * 128;

    float acc[8][8];
    #pragma unroll
    for (int i = 0; i < 8; i++)
        #pragma unroll
        for (int j = 0; j < 8; j++) acc[i][j] = 0.f;

    for (int k0 = 0; k0 < 128; k0 += 16) {
        #pragma unroll
        for (int j = 0; j < 8; j++) {
            int idx = j * 256 + tid;
            int r = idx >> 4, kk = idx & 15;
            As[r][kk] = A[(row0 + r) * (size_t)lda + k0 + kk];
        }
        #pragma unroll
        for (int i = 0; i < 2; i++) {
            int idx = i * 256 + tid;
            int kk = idx >> 5, c4 = idx & 31;
            Bs[kk][c4] = *reinterpret_cast<const float4*>(Bm + (size_t)(k0 + kk) * 128 + c4 * 4);
        }
        __syncthreads();
        #pragma unroll
        for (int kk = 0; kk < 16; kk++) {
            float a[8];
            #pragma unroll
            for (int i = 0; i < 8; i++) a[i] = As[ty * 8 + i][kk];
            float4 bv0 = Bs[kk][tx * 2];
            float4 bv1 = Bs[kk][tx * 2 + 1];
            float bjs[8] = {bv0.x, bv0.y, bv0.z, bv0.w, bv1.x, bv1.y, bv1.z, bv1.w};
            #pragma unroll
            for (int i = 0; i < 8; i++)
                #pragma unroll
                for (int j = 0; j < 8; j++)
                    acc[i][j] = fmaf(a[i], bjs[j], acc[i][j]);
        }
        __syncthreads();
    }
    float bb[8] = {0,0,0,0,0,0,0,0};
    if (bias) {
        #pragma unroll
        for (int j = 0; j < 8; j++) bb[j] = bias[tx * 8 + j];
    }
    #pragma unroll
    for (int i = 0; i < 8; i++) {
        size_t gr = row0 + ty * 8 + i;
        float* cp = C + gr * (size_t)ldc + blockIdx.y * 128 + tx * 8;
        float4 o0 = make_float4(acc[i][0]+bb[0], acc[i][1]+bb[1], acc[i][2]+bb[2], acc[i][3]+bb[3]);
        float4 o1 = make_float4(acc[i][4]+bb[4], acc[i][5]+bb[5], acc[i][6]+bb[6], acc[i][7]+bb[7]);
        *reinterpret_cast<float4*>(cp)     = o0;
        *reinterpret_cast<float4*>(cp + 4) = o1;
    }
}

// ---------------- fold biases / timestamp gates ----------------
// channels: 0..2: px[g]+bg[g]; 3: px3+Tt*Wts4+Dt*Wts5+bg3; 4: T1*D1; 5: T2*D2
__global__ __launch_bounds__(256) void prep_kernel(
    const float* __restrict__ inputs, const float* __restrict__ Wts, const float* __restrict__ bg)
{
    int idx = blockIdx.x * 256 + threadIdx.x;
    int r = idx >> 7, k = idx & 127;
    float Tt = inputs[(size_t)r * 130];
    float Dt = inputs[(size_t)r * 130 + 1];
    const float* px = g_px8 + (size_t)r * 1024;
    float* o = g_pxg + (size_t)r * 768;
    o[k]        = px[k]        + bg[k];
    o[Hn + k]   = px[Hn + k]   + bg[Hn + k];
    o[2*Hn + k] = px[2*Hn + k] + bg[2*Hn + k];
    o[3*Hn + k] = px[3*Hn + k] + fmaf(Tt, Wts[4*Hn + k], fmaf(Dt, Wts[5*Hn + k], bg[3*Hn + k]));
    float T1 = sigf(px[4*Hn + k] + sigf(Tt * Wts[k])        + bg[4*Hn + k]);
    float T2 = sigf(px[5*Hn + k] + sigf(Tt * Wts[Hn + k])   + bg[5*Hn + k]);
    float D1 = sigf(px[6*Hn + k] + sigf(Dt * Wts[2*Hn + k]) + bg[6*Hn + k]);
    float D2 = sigf(px[7*Hn + k] + sigf(Dt * Wts[3*Hn + k]) + bg[7*Hn + k]);
    o[4*Hn + k] = T1 * D1;
    o[5*Hn + k] = T2 * D2;
}

// ---------------- recurrent kernel: one block per batch (kl-balanced order) ----------------
__global__ __launch_bounds__(512, 2) void recur_kernel(
    const float* __restrict__ Wh,
    const float* __restrict__ Wattn,
    const float* __restrict__ battn,
    const int*   __restrict__ kl_arr,
    const float* __restrict__ y_all,
    float* __restrict__ out)
{
    const int b    = g_order[blockIdx.x];
    const int tid  = threadIdx.x;
    const int lane = tid & 31;
    const int warp = tid >> 5;
    const int kl   = kl_arr[b];

    __shared__ float h_sm[SHn];      // h state (== h_new on executed steps)
    __shared__ float c_sm[SHn];
    __shared__ float qp_sm[SHn];
    __shared__ float ctx_sm[SHn];
    __shared__ float at_sm[SHn];
    __shared__ float pre_sm[4][SHn];
    __shared__ float sc_sm[Sn][Tn];
    __shared__ float nvinv_sm[Tn];
    __shared__ float red_sm[16];

    for (int i = tid; i < SHn; i += 512) { h_sm[i] = 0.f; c_sm[i] = 0.f; }
    if (tid < Tn) nvinv_sm[tid] = 1.f / (float)max(g_nv[tid], 1);
    __syncthreads();

    const size_t bbase = (size_t)b * Tn * Sn * Hn;
    float*       pkb  = g_pk  + bbase;
    float*       pvb  = g_pv  + bbase;
    const float* qpb  = g_qp  + bbase;
    const float* pxb  = g_pxg + (size_t)b * Tn * 768;
    float*       hseq = out + bbase;
    float lsum = 0.f;
    const float scale = 0.088388347648318447f; // 1/sqrt(128)

    for (int t = 0; t < kl; t++) {
        const float* qpt = qpb + (size_t)t * SHn;
        const float* pxt = pxb + (size_t)t * 768;
        for (int i = tid; i < SHn; i += 512) qp_sm[i] = qpt[i];
        __syncthreads();   // qp ready; prior step's pk/pv global writes visible

        if (t > 0) {
            // scores: one warp per (s, t') pair
            for (int p = warp; p < Sn * t; p += 16) {
                int tp = p / Sn, s = p - tp * Sn;
                const float* pkrow = pkb + ((size_t)tp * Sn + s) * Hn;
                const float* q = qp_sm + s * Hn;
                float a = 0.f;
                #pragma unroll
                for (int h = 0; h < 4; h++) a = fmaf(q[lane + h*32], pkrow[lane + h*32], a);
                #pragma unroll
                for (int o = 16; o; o >>= 1) a += __shfl_xor_sync(0xffffffffu, a, o);
                if (lane == 0) sc_sm[s][tp] = a * scale;
            }
            __syncthreads();
            // softmax over t' < t, warp s
            if (warp < Sn) {
                float* sc = sc_sm[warp];
                float m = -1e30f;
                for (int tp = lane; tp < t; tp += 32) m = fmaxf(m, sc[tp]);
                #pragma unroll
                for (int o = 16; o; o >>= 1) m = fmaxf(m, __shfl_xor_sync(0xffffffffu, m, o));
                float sum = 0.f;
                for (int tp = lane; tp < t; tp += 32) { float e = __expf(sc[tp] - m); sc[tp] = e; sum += e; }
                #pragma unroll
                for (int o = 16; o; o >>= 1) sum += __shfl_xor_sync(0xffffffffu, sum, o);
                float inv = 1.f / sum;
                for (int tp = lane; tp < t; tp += 32) sc[tp] *= inv;
            }
            __syncthreads();
            // ctx = weights @ pv
            for (int i = tid; i < SHn; i += 512) {
                int s = i >> 7;
                const float* pvp = pvb + i;
                float a = 0.f;
                for (int tp = 0; tp < t; tp++) a = fmaf(sc_sm[s][tp], pvp[(size_t)tp * SHn], a);
                ctx_sm[i] = a;
            }
            __syncthreads();
            // at = ctx @ Wattn[3] + battn[3]
            {
                int j = tid >> 7, k = tid & 127;
                const float* W3 = Wattn + 3 * Hn * Hn + k;
                bool has2 = (j < 2);
                const float* c0 = ctx_sm + j * Hn;
                const float* c1 = ctx_sm + (j + 4) * Hn;
                const float* c2 = ctx_sm + (has2 ? (j + 8) : j) * Hn;
                float a0 = 0.f, a1 = 0.f, a2 = 0.f;
                for (int h4 = 0; h4 < Hn; h4 += 4) {
                    float w0 = W3[(h4+0)*Hn], w1 = W3[(h4+1)*Hn], w2 = W3[(h4+2)*Hn], w3 = W3[(h4+3)*Hn];
                    float4 v0 = *reinterpret_cast<const float4*>(c0 + h4);
                    a0 = fmaf(v0.x,w0, fmaf(v0.y,w1, fmaf(v0.z,w2, fmaf(v0.w,w3, a0))));
                    float4 v1 = *reinterpret_cast<const float4*>(c1 + h4);
                    a1 = fmaf(v1.x,w0, fmaf(v1.y,w1, fmaf(v1.z,w2, fmaf(v1.w,w3, a1))));
                    if (has2) {
                        float4 v2 = *reinterpret_cast<const float4*>(c2 + h4);
                        a2 = fmaf(v2.x,w0, fmaf(v2.y,w1, fmaf(v2.z,w2, fmaf(v2.w,w3, a2))));
                    }
                }
                float bb = battn[3 * Hn + k];
                at_sm[j * Hn + k]       = a0 + bb;
                at_sm[(j + 4) * Hn + k] = a1 + bb;
                if (has2) at_sm[(j + 8) * Hn + k] = a2 + bb;
            }
        } else {
            for (int i = tid; i < SHn; i += 512) at_sm[i] = 1.f;
        }

        // ph = h @ Wh[g] + folded px   (thread = (g,k); s register-blocked; h broadcast from smem)
        {
            int g = tid >> 7, k = tid & 127;
            const float* Wg = Wh + (size_t)g * Hn * Hn + k;
            float acc[Sn];
            #pragma unroll
            for (int s = 0; s < Sn; s++) acc[s] = 0.f;
            for (int h4 = 0; h4 < Hn; h4 += 4) {
                float w0 = Wg[(h4+0)*Hn], w1 = Wg[(h4+1)*Hn], w2 = Wg[(h4+2)*Hn], w3 = Wg[(h4+3)*Hn];
                #pragma unroll
                for (int s = 0; s < Sn; s++) {
                    float4 hv = *reinterpret_cast<const float4*>(h_sm + s * Hn + h4);
                    acc[s] = fmaf(hv.x,w0, fmaf(hv.y,w1, fmaf(hv.z,w2, fmaf(hv.w,w3, acc[s]))));
                }
            }
            float p = pxt[g * Hn + k];
            #pragma unroll
            for (int s = 0; s < Sn; s++) pre_sm[g][s * Hn + k] = acc[s] + p;
        }
        __syncthreads();   // pre_sm/at_sm ready; h_sm reads done -> safe to overwrite

        // gates + state update + hseq + loss (mask true on all executed steps)
        {
            float yv = y_all[b * Tn + t];
            float invnv = nvinv_sm[t];
            float lstep = 0.f;
            for (int i = tid; i < SHn; i += 512) {
                int k = i & 127;
                float it  = sigf(pre_sm[0][i]);
                float ft  = sigf(pre_sm[1][i]);
                float ctd = tanhf(pre_sm[2][i]);
                float ot  = sigf(pre_sm[3][i]);
                float at  = at_sm[i];
                float td1 = pxt[4 * Hn + k];
                float td2 = pxt[5 * Hn + k];
                float itp = it * at, ftp = ft * at;
                float c = c_sm[i];
                float base = ftp * c;
                float ic = itp * ctd;
                float chat = fmaf(ic, td1, base);
                float cnew = fmaf(ic, td2, base);
                float hnew = ot * tanhf(chat);
                c_sm[i] = cnew;
                h_sm[i] = hnew;
                hseq[(size_t)t * SHn + i] = hnew;
                float pcl = fminf(fmaxf(hnew, 1e-7f), 1.f - 1e-7f);
                lstep += -(yv * logf(pcl) + (1.f - yv) * log1pf(-pcl));
            }
            lsum = fmaf(lstep, invnv * (1.f / (float)SHn), lsum);
        }
        __syncthreads();   // h_sm (= h_new) ready for pk/pv + next-step ph

        // pk[t] = h@Wattn1 + battn1 ; pv[t] = h@Wattn2 + battn2
        {
            int m = tid >> 8, j = (tid >> 7) & 1, k = tid & 127;
            const float* W = Wattn + (size_t)(1 + m) * Hn * Hn + k;
            float acc[5];
            #pragma unroll
            for (int q = 0; q < 5; q++) acc[q] = 0.f;
            for (int h4 = 0; h4 < Hn; h4 += 4) {
                float w0 = W[(h4+0)*Hn], w1 = W[(h4+1)*Hn], w2 = W[(h4+2)*Hn], w3 = W[(h4+3)*Hn];
                #pragma unroll
                for (int q = 0; q < 5; q++) {
                    float4 hv = *reinterpret_cast<const float4*>(h_sm + (2*q + j) * Hn + h4);
                    acc[q] = fmaf(hv.x,w0, fmaf(hv.y,w1, fmaf(hv.z,w2, fmaf(hv.w,w3, acc[q]))));
                }
            }
            float bb = battn[(1 + m) * Hn + k];
            float* dst = (m == 0) ? pkb : pvb;
            #pragma unroll
            for (int q = 0; q < 5; q++)
                dst[((size_t)t * Sn + (2*q + j)) * Hn + k] = acc[q] + bb;
        }
        // no trailing sync needed: next-iter top sync orders these writes
    }

    // zero tail of hseq for masked steps
    for (size_t i = tid; i < (size_t)(Tn - kl) * SHn; i += 512)
        hseq[(size_t)kl * SHn + i] = 0.f;

    // final h, c
    {
        float* hout = out + HSEQ_SZ + (size_t)b * SHn;
        float* cout = out + HSEQ_SZ + (size_t)Bn * SHn + (size_t)b * SHn;
        __syncthreads();
        for (int i = tid; i < SHn; i += 512) { hout[i] = h_sm[i]; cout[i] = c_sm[i]; }
    }

    // loss partial (deterministic final reduce in separate kernel)
    #pragma unroll
    for (int o = 16; o; o >>= 1) lsum += __shfl_xor_sync(0xffffffffu, lsum, o);
    if (lane == 0) red_sm[warp] = lsum;
    __syncthreads();
    if (tid == 0) {
        float s = 0.f;
        #pragma unroll
        for (int w = 0; w < 16; w++) s += red_sm[w];
        g_losspart[b] = s;
    }
}

// ---------------- deterministic loss reduction ----------------
__global__ void loss_final(float* __restrict__ out) {
    if (threadIdx.x == 0) {
        float s = 0.f;
        for (int b = 0; b < Bn; b++) s += g_losspart[b];
        out[LOSS_IDX] = s;
    }
}

extern "C" void kernel_launch(void* const* d_in, const int* in_sizes, int n_in,
                              void* d_out, int out_size) {
    const float* inputs = (const float*)d_in[0];
    const float* x_q    = (const float*)d_in[1];
    const float* y_all  = (const float*)d_in[2];
    const int*   kl     = (const int*)  d_in[3];
    const float* Wx     = (const float*)d_in[4];
    const float* Wh     = (const float*)d_in[5];
    const float* Wts    = (const float*)d_in[6];
    const float* bg     = (const float*)d_in[7];
    const float* Wa     = (const float*)d_in[8];
    const float* ba     = (const float*)d_in[9];
    const float* Wattn  = (const float*)d_in[10];
    const float* battn  = (const float*)d_in[11];
    float* out = (float*)d_out;

    float *px8, *qp, *wfused, *bfused;
    cudaGetSymbolAddress((void**)&px8,    g_px8);
    cudaGetSymbolAddress((void**)&qp,     g_qp);
    cudaGetSymbolAddress((void**)&wfused, g_wfused);
    cudaGetSymbolAddress((void**)&bfused, g_bfused);

    nv_kernel<<<1, 64>>>(kl);
    order_kernel<<<1, 32>>>(kl);

    // px8 = xt @ Wx[g], g in grid.y
    gemm128<<<dim3(BTn/128, 8), 256>>>(inputs + 2, 130, Wx, Hn*Hn, nullptr, px8, 1024);
    // Wfused = Wa @ Wattn[0]; bfused = ba @ Wattn[0] + battn[0]
    gemm128<<<dim3(1, 1), 256>>>(Wa, Hn, Wattn, 0, nullptr, wfused, Hn);
    bfuse_kernel<<<1, Hn>>>(ba, Wattn, battn);
    // qp = x_q @ Wfused + bfused   (fused double-GEMM)
    gemm128<<<dim3(BTSn/128, 1), 256>>>(x_q, Hn, wfused, 0, bfused, qp, Hn);
    // fold biases / timestamp gates
    prep_kernel<<<BTn*Hn/256, 256>>>(inputs, Wts, bg);
    // recurrence: one block per batch, kl-balanced placement
    recur_kernel<<<Bn, 512>>>(Wh, Wattn, battn, kl, y_all, out);
    // deterministic loss sum
    loss_final<<<1, 32>>>(out);
}